// round 5
// baseline (speedup 1.0000x reference)
#include <cuda_runtime.h>
#include <math.h>

// ----------------------------------------------------------------------------
// QuantumBranch, fused single kernel (round 5).
// expz0(t) = degree-12 trig polynomial in (pi*t), exactly.
// Per block: 25 circuit samples -> exact real DFT -> 2048-interval CENTERED
// LINEAR table (float2 = value, slope*h) built lane-parallel in smem.
// Main path is straight-line: 8 elements/thread, the two LDG.128 are issued
// BEFORE the preamble so DRAM latency overlaps the table build.
// Index extraction uses the 2^23 mantissa trick: no F2I/I2F CVTs.
// Linear-interp error f''*h^2/8 ~ 1e-7*f''  << 1e-3 tolerance.
// ----------------------------------------------------------------------------

#define NSAMP 25
#define NHARM 12
#define TBL   2048
#define THREADS 256
#define PI_F  3.14159265358979323846f
#define TWO_PI_F 6.28318530717958647692f
#define MAGIC 8388608.0f   // 2^23: RN add puts round(x) in low mantissa bits

struct cf { float re, im; };

__device__ __forceinline__ void gate1q(cf* s, int wire,
    float u00r, float u00i, float u01r, float u01i,
    float u10r, float u10i, float u11r, float u11i)
{
    const int str = 4 >> wire;
    #pragma unroll
    for (int k = 0; k < 8; k++) {
        if (k & str) continue;
        cf a = s[k], b = s[k + str];
        s[k].re       = u00r*a.re - u00i*a.im + u01r*b.re - u01i*b.im;
        s[k].im       = u00r*a.im + u00i*a.re + u01r*b.im + u01i*b.re;
        s[k + str].re = u10r*a.re - u10i*a.im + u11r*b.re - u11i*b.im;
        s[k + str].im = u10r*a.im + u10i*a.re + u11r*b.im + u11i*b.re;
    }
}

__device__ __forceinline__ void cnot(cf* s, int ctrl, int tgt)
{
    const int sc = 4 >> ctrl, st = 4 >> tgt;
    #pragma unroll
    for (int k = 0; k < 8; k++) {
        if (!(k & sc) || (k & st)) continue;
        cf tmp = s[k]; s[k] = s[k + st]; s[k + st] = tmp;
    }
}

__device__ void ansatz(cf* s, const float* th)
{
    #pragma unroll
    for (int i = 0; i < 3; i++) {
        float a = th[i*3 + 0];
        float c, z; __sincosf(0.5f*a, &z, &c);
        gate1q(s, i, c, -z, 0.f, 0.f, 0.f, 0.f, c, z);          // RZ
        a = th[i*3 + 1];
        __sincosf(0.5f*a, &z, &c);
        gate1q(s, i, c, 0.f, 0.f, -z, 0.f, -z, c, 0.f);         // RX
        a = th[i*3 + 2];
        __sincosf(0.5f*a, &z, &c);
        gate1q(s, i, c, -z, 0.f, 0.f, 0.f, 0.f, c, z);          // RZ
    }
    cnot(s, 0, 1); cnot(s, 1, 2); cnot(s, 2, 0);
}

__device__ void feature(cf* s, float t)
{
    #pragma unroll
    for (int i = 0; i < 3; i++) {
        float c, z;
        __sincosf(0.5f * PI_F * t * (float)(i + 1), &z, &c);
        gate1q(s, i, c, 0.f, -z, 0.f, z, 0.f, c, 0.f);          // RY
    }
}

__device__ float eval_circuit(const float* theta, float t)
{
    cf s[8];
    #pragma unroll
    for (int k = 0; k < 8; k++) { s[k].re = 0.f; s[k].im = 0.f; }
    s[0].re = 1.f;
    ansatz(s, theta);
    feature(s, t);
    ansatz(s, theta + 9);
    feature(s, t);
    ansatz(s, theta + 18);
    float e = 0.f;
    #pragma unroll
    for (int k = 0; k < 8; k++) {
        float p = s[k].re*s[k].re + s[k].im*s[k].im;
        e += (k < 4) ? p : -p;   // Z on qubit 0 (bit value 4)
    }
    return e;
}

__device__ __forceinline__ float interp(float tt, const float2* tbl)
{
    float y = fmaf(tt, (float)TBL, MAGIC);          // round(tt*TBL) in mantissa
    int   i = __float_as_int(y) & 0xFFF;            // 0..2048
    float r = y - MAGIC;                            // exact: round(tt*TBL)
    float u = fmaf(tt, (float)TBL, -r);             // u in [-0.5, 0.5]
    float2 c = tbl[i];
    return fmaf(u, c.y, c.x);
}

__global__ void __launch_bounds__(THREADS, 8)
fused_kernel(const float* __restrict__ theta,
             const float* __restrict__ t,
             float* __restrict__ out, int n)
{
    __shared__ float2 tbl[TBL + 1];
    __shared__ float fs[NSAMP];
    __shared__ float ca[NHARM + 1], cb[NHARM + 1];

    const int tid = threadIdx.x;
    const int base = (blockIdx.x * THREADS + tid) * 8;
    const bool full = (base + 7) < n;

    // ---- 0) issue main-path loads FIRST: DRAM latency overlaps the preamble
    float4 ta, tb2;
    if (full) {
        ta  = __ldg(reinterpret_cast<const float4*>(t + base));
        tb2 = __ldg(reinterpret_cast<const float4*>(t + base) + 1);
    }

    // ---- 1) circuit samples (warp 0, 25 lanes) -------------------------------
    if (tid < NSAMP)
        fs[tid] = eval_circuit(theta, 2.0f * (float)tid / 25.0f);
    __syncthreads();

    // ---- 2) exact real DFT on 25 samples -------------------------------------
    if (tid < NSAMP) {
        float sum = 0.f;
        if (tid == 0) {
            for (int m = 0; m < NSAMP; m++) sum += fs[m];
            ca[0] = sum * (1.0f / 25.0f);
            cb[0] = 0.f;
        } else if (tid <= NHARM) {
            for (int m = 0; m < NSAMP; m++) {
                int r = (tid * m) % 25;
                float c, s; __sincosf(TWO_PI_F * (float)r * (1.0f/25.0f), &s, &c);
                sum += fs[m] * c;
            }
            ca[tid] = sum * (2.0f / 25.0f);
        } else {
            int k = tid - NHARM;
            for (int m = 0; m < NSAMP; m++) {
                int r = (k * m) % 25;
                float c, s; __sincosf(TWO_PI_F * (float)r * (1.0f/25.0f), &s, &c);
                sum += fs[m] * s;
            }
            cb[k] = sum * (2.0f / 25.0f);
        }
    }
    __syncthreads();

    // ---- 3) centered-linear table: (f(t_e), f'(t_e)*h), lane-parallel --------
    for (int e = tid; e <= TBL; e += THREADS) {
        float tt = (float)e * (1.0f / (float)TBL);
        float c1v, s1v; __sincosf(PI_F * tt, &s1v, &c1v);
        float f = fmaf(ca[1], c1v, ca[0]);
        f = fmaf(cb[1], s1v, f);
        float g = cb[1]*c1v - ca[1]*s1v;
        const float twoc = c1v + c1v;
        float ckm = 1.f, ck = c1v, skm = 0.f, sk = s1v;
        #pragma unroll
        for (int k = 2; k <= NHARM; k++) {
            float cn = fmaf(twoc, ck, -ckm);
            float sn = fmaf(twoc, sk, -skm);
            f = fmaf(ca[k], cn, f);
            f = fmaf(cb[k], sn, f);
            g = fmaf((float)k, cb[k]*cn - ca[k]*sn, g);
            ckm = ck; ck = cn; skm = sk; sk = sn;
        }
        tbl[e] = make_float2(f, g * (PI_F / (float)TBL));
    }
    __syncthreads();

    // ---- 4) straight-line main path: 8 elements/thread -----------------------
    if (full) {
        float4 oa, ob;
        oa.x = interp(ta.x,  tbl);
        oa.y = interp(ta.y,  tbl);
        oa.z = interp(ta.z,  tbl);
        oa.w = interp(ta.w,  tbl);
        *reinterpret_cast<float4*>(out + base) = oa;
        ob.x = interp(tb2.x, tbl);
        ob.y = interp(tb2.y, tbl);
        ob.z = interp(tb2.z, tbl);
        ob.w = interp(tb2.w, tbl);
        *(reinterpret_cast<float4*>(out + base) + 1) = ob;
    } else {
        for (int i = base; i < n; i++)
            out[i] = interp(t[i], tbl);
    }
}

extern "C" void kernel_launch(void* const* d_in, const int* in_sizes, int n_in,
                              void* d_out, int out_size)
{
    const float* t;
    const float* theta;
    if (n_in >= 2 && in_sizes[0] == 27 && in_sizes[1] != 27) {
        theta = (const float*)d_in[0];
        t     = (const float*)d_in[1];
    } else {
        t     = (const float*)d_in[0];
        theta = (const float*)d_in[1];
    }
    float* out = (float*)d_out;
    const int n = out_size;

    // 8 elements per thread, straight-line; n = 2^21 -> exactly 1024 blocks,
    // one wave at 8 blocks/SM (16.6 KB smem, <=32 regs via launch_bounds).
    const int blocks = (n + THREADS * 8 - 1) / (THREADS * 8);
    fused_kernel<<<blocks, THREADS>>>(theta, t, out, n);
}

// round 6
// speedup vs baseline: 1.1983x; 1.1983x over previous
#include <cuda_runtime.h>
#include <math.h>

// ----------------------------------------------------------------------------
// QuantumBranch, fused single kernel (round 6).
// expz0(t) = degree-12 trig polynomial in (pi*t), exactly.
// Per block: 25 circuit samples -> exact real DFT -> 512-entry CENTERED cubic
// table (float4 power-basis coeffs, u in [-0.5,0.5]) in smem.
// Inputs are prefetched into an smem staging buffer BEFORE the preamble
// (overlaps DRAM latency without register liveness across barriers -> no
// spills under the 32-reg / 8-blocks-per-SM cap).
// Main path: LDS.128 (staged t) -> magic-round index (no CVTs) -> LDS.128
// table -> 3 FMA -> STG.128.  One wave: 1024 blocks, 2048 elem/block.
// ----------------------------------------------------------------------------

#define NSAMP 25
#define NHARM 12
#define TBL   512
#define THREADS 256
#define ELEMS_PER_BLOCK (THREADS * 8)
#define PI_F  3.14159265358979323846f
#define TWO_PI_F 6.28318530717958647692f
#define MAGIC 8388608.0f   // 2^23

struct cf { float re, im; };

__device__ __forceinline__ void gate1q(cf* s, int wire,
    float u00r, float u00i, float u01r, float u01i,
    float u10r, float u10i, float u11r, float u11i)
{
    const int str = 4 >> wire;
    #pragma unroll
    for (int k = 0; k < 8; k++) {
        if (k & str) continue;
        cf a = s[k], b = s[k + str];
        s[k].re       = u00r*a.re - u00i*a.im + u01r*b.re - u01i*b.im;
        s[k].im       = u00r*a.im + u00i*a.re + u01r*b.im + u01i*b.re;
        s[k + str].re = u10r*a.re - u10i*a.im + u11r*b.re - u11i*b.im;
        s[k + str].im = u10r*a.im + u10i*a.re + u11r*b.im + u11i*b.re;
    }
}

__device__ __forceinline__ void cnot(cf* s, int ctrl, int tgt)
{
    const int sc = 4 >> ctrl, st = 4 >> tgt;
    #pragma unroll
    for (int k = 0; k < 8; k++) {
        if (!(k & sc) || (k & st)) continue;
        cf tmp = s[k]; s[k] = s[k + st]; s[k + st] = tmp;
    }
}

__device__ void ansatz(cf* s, const float* th)
{
    #pragma unroll
    for (int i = 0; i < 3; i++) {
        float a = th[i*3 + 0];
        float c, z; __sincosf(0.5f*a, &z, &c);
        gate1q(s, i, c, -z, 0.f, 0.f, 0.f, 0.f, c, z);          // RZ
        a = th[i*3 + 1];
        __sincosf(0.5f*a, &z, &c);
        gate1q(s, i, c, 0.f, 0.f, -z, 0.f, -z, c, 0.f);         // RX
        a = th[i*3 + 2];
        __sincosf(0.5f*a, &z, &c);
        gate1q(s, i, c, -z, 0.f, 0.f, 0.f, 0.f, c, z);          // RZ
    }
    cnot(s, 0, 1); cnot(s, 1, 2); cnot(s, 2, 0);
}

__device__ void feature(cf* s, float t)
{
    #pragma unroll
    for (int i = 0; i < 3; i++) {
        float c, z;
        __sincosf(0.5f * PI_F * t * (float)(i + 1), &z, &c);
        gate1q(s, i, c, 0.f, -z, 0.f, z, 0.f, c, 0.f);          // RY
    }
}

__device__ float eval_circuit(const float* theta, float t)
{
    cf s[8];
    #pragma unroll
    for (int k = 0; k < 8; k++) { s[k].re = 0.f; s[k].im = 0.f; }
    s[0].re = 1.f;
    ansatz(s, theta);
    feature(s, t);
    ansatz(s, theta + 9);
    feature(s, t);
    ansatz(s, theta + 18);
    float e = 0.f;
    #pragma unroll
    for (int k = 0; k < 8; k++) {
        float p = s[k].re*s[k].re + s[k].im*s[k].im;
        e += (k < 4) ? p : -p;   // Z on qubit 0 (bit value 4)
    }
    return e;
}

// Trig-poly value f and scaled derivative D = f'(t)*h at t.
__device__ __forceinline__ void poly_fd(float tt, const float* ca,
                                        const float* cb, float& f, float& D)
{
    float c1v, s1v; __sincosf(PI_F * tt, &s1v, &c1v);
    f = fmaf(ca[1], c1v, ca[0]);
    f = fmaf(cb[1], s1v, f);
    float g = cb[1]*c1v - ca[1]*s1v;
    const float twoc = c1v + c1v;
    float ckm = 1.f, ck = c1v, skm = 0.f, sk = s1v;
    #pragma unroll
    for (int k = 2; k <= NHARM; k++) {
        float cn = fmaf(twoc, ck, -ckm);
        float sn = fmaf(twoc, sk, -skm);
        f = fmaf(ca[k], cn, f);
        f = fmaf(cb[k], sn, f);
        g = fmaf((float)k, cb[k]*cn - ca[k]*sn, g);
        ckm = ck; ck = cn; skm = sk; sk = sn;
    }
    D = g * (PI_F / (float)TBL);
}

__device__ __forceinline__ float interp(float tt, const float4* tbl)
{
    float y = fmaf(tt, (float)TBL, MAGIC);     // round(tt*TBL) in mantissa
    int   i = __float_as_int(y) & 1023;
    i = min(i, TBL);
    float r = y - MAGIC;
    float u = fmaf(tt, (float)TBL, -r);        // u in [-0.5, 0.5]
    float4 c = tbl[i];
    return fmaf(fmaf(fmaf(c.w, u, c.z), u, c.y), u, c.x);
}

__global__ void __launch_bounds__(THREADS, 8)
fused_kernel(const float* __restrict__ theta,
             const float* __restrict__ t,
             float* __restrict__ out, int n)
{
    __shared__ float4 tbl[TBL + 1];      // 8.2 KB
    __shared__ float4 tin[2 * THREADS];  // 8.0 KB staging
    __shared__ float fs[NSAMP];
    __shared__ float ca[NHARM + 1], cb[NHARM + 1];

    const int tid = threadIdx.x;
    const int vbase = blockIdx.x * (ELEMS_PER_BLOCK / 4);   // float4 index
    const bool full = (vbase + 2 * THREADS) * 4 <= n;

    // ---- 0) stage this block's inputs in smem (overlaps preamble) -----------
    if (full) {
        const float4* in4 = reinterpret_cast<const float4*>(t);
        tin[tid]           = __ldg(in4 + vbase + tid);
        tin[tid + THREADS] = __ldg(in4 + vbase + THREADS + tid);
    }

    // ---- 1) circuit samples (warp 0, 25 lanes) -------------------------------
    if (tid < NSAMP)
        fs[tid] = eval_circuit(theta, 2.0f * (float)tid / 25.0f);
    __syncthreads();

    // ---- 2) exact real DFT on 25 samples -------------------------------------
    if (tid < NSAMP) {
        float sum = 0.f;
        if (tid == 0) {
            for (int m = 0; m < NSAMP; m++) sum += fs[m];
            ca[0] = sum * (1.0f / 25.0f);
            cb[0] = 0.f;
        } else if (tid <= NHARM) {
            for (int m = 0; m < NSAMP; m++) {
                int r = (tid * m) % 25;
                float c, s; __sincosf(TWO_PI_F * (float)r * (1.0f/25.0f), &s, &c);
                sum += fs[m] * c;
            }
            ca[tid] = sum * (2.0f / 25.0f);
        } else {
            int k = tid - NHARM;
            for (int m = 0; m < NSAMP; m++) {
                int r = (k * m) % 25;
                float c, s; __sincosf(TWO_PI_F * (float)r * (1.0f/25.0f), &s, &c);
                sum += fs[m] * s;
            }
            cb[k] = sum * (2.0f / 25.0f);
        }
    }
    __syncthreads();

    // ---- 3) centered cubic table: entry e covers t in [(e-.5)h, (e+.5)h] -----
    for (int e = tid; e <= TBL; e += THREADS) {
        const float h = 1.0f / (float)TBL;
        float f0, D0, f1, D1;
        poly_fd(((float)e - 0.5f) * h, ca, cb, f0, D0);
        poly_fd(((float)e + 0.5f) * h, ca, cb, f1, D1);
        // Hermite power basis in v = u + 0.5 on [0,1]
        float h0 = f0;
        float h1 = D0;
        float h2 = 3.f*(f1 - f0) - 2.f*D0 - D1;
        float h3 = 2.f*(f0 - f1) + D0 + D1;
        // re-expand in u = v - 0.5 (u in [-0.5, 0.5])
        float q0 = h0 + 0.5f*h1 + 0.25f*h2 + 0.125f*h3;
        float q1 = h1 + h2 + 0.75f*h3;
        float q2 = h2 + 1.5f*h3;
        float q3 = h3;
        tbl[e] = make_float4(q0, q1, q2, q3);
    }
    __syncthreads();

    // ---- 4) main path: 8 elements/thread from staged smem --------------------
    if (full) {
        float4* out4 = reinterpret_cast<float4*>(out);
        #pragma unroll
        for (int j = 0; j < 2; j++) {
            float4 tv = tin[tid + j * THREADS];
            float4 ov;
            ov.x = interp(tv.x, tbl);
            ov.y = interp(tv.y, tbl);
            ov.z = interp(tv.z, tbl);
            ov.w = interp(tv.w, tbl);
            out4[vbase + j * THREADS + tid] = ov;
        }
    } else {
        for (int i = vbase * 4 + tid; i < n; i += THREADS)
            out[i] = interp(t[i], tbl);
    }
}

extern "C" void kernel_launch(void* const* d_in, const int* in_sizes, int n_in,
                              void* d_out, int out_size)
{
    const float* t;
    const float* theta;
    if (n_in >= 2 && in_sizes[0] == 27 && in_sizes[1] != 27) {
        theta = (const float*)d_in[0];
        t     = (const float*)d_in[1];
    } else {
        t     = (const float*)d_in[0];
        theta = (const float*)d_in[1];
    }
    float* out = (float*)d_out;
    const int n = out_size;

    // 2048 elements/block -> n = 2^21 gives exactly 1024 blocks: one wave
    // (152 SMs x 8 resident blocks = 1216 slots).
    const int blocks = (n + ELEMS_PER_BLOCK - 1) / ELEMS_PER_BLOCK;
    fused_kernel<<<blocks, THREADS>>>(theta, t, out, n);
}

// round 7
// speedup vs baseline: 1.5978x; 1.3333x over previous
#include <cuda_runtime.h>
#include <math.h>

// ----------------------------------------------------------------------------
// QuantumBranch, two-kernel split (round 7).
// expz0(t) = degree-12 trig polynomial in (pi*t), exactly.
// Round-6 lesson: the fused design re-ran the (spilled, serial) circuit+DFT
// preamble in all 1024 blocks ~ 15 us of the 20. Split it out:
//   K1 (1 block): 25 circuit samples -> exact real DFT -> 256-entry cubic
//      table (float4 power basis) -> __device__ global.  All __sincosf.
//   K2 (2048 blocks): table global->smem (4 KB), then 1 float4/thread:
//      LDG.128 -> 4x (index + LDS.128 + 3 FMA) -> STG.128.
// Cubic error (12pi)^4 h^4/384 ~ 1.2e-6 at TBL=256  << 1e-3 tolerance.
// ----------------------------------------------------------------------------

#define NSAMP 25
#define NHARM 12
#define TBL   256
#define THREADS 256
#define PI_F  3.14159265358979323846f
#define TWO_PI_F 6.28318530717958647692f

__device__ float4 g_table[TBL];

struct cf { float re, im; };

__device__ __forceinline__ void gate1q(cf* s, int wire,
    float u00r, float u00i, float u01r, float u01i,
    float u10r, float u10i, float u11r, float u11i)
{
    const int str = 4 >> wire;
    #pragma unroll
    for (int k = 0; k < 8; k++) {
        if (k & str) continue;
        cf a = s[k], b = s[k + str];
        s[k].re       = u00r*a.re - u00i*a.im + u01r*b.re - u01i*b.im;
        s[k].im       = u00r*a.im + u00i*a.re + u01r*b.im + u01i*b.re;
        s[k + str].re = u10r*a.re - u10i*a.im + u11r*b.re - u11i*b.im;
        s[k + str].im = u10r*a.im + u10i*a.re + u11r*b.im + u11i*b.re;
    }
}

__device__ __forceinline__ void cnot(cf* s, int ctrl, int tgt)
{
    const int sc = 4 >> ctrl, st = 4 >> tgt;
    #pragma unroll
    for (int k = 0; k < 8; k++) {
        if (!(k & sc) || (k & st)) continue;
        cf tmp = s[k]; s[k] = s[k + st]; s[k + st] = tmp;
    }
}

__device__ void ansatz(cf* s, const float* th)
{
    #pragma unroll
    for (int i = 0; i < 3; i++) {
        float a = th[i*3 + 0];
        float c, z; __sincosf(0.5f*a, &z, &c);
        gate1q(s, i, c, -z, 0.f, 0.f, 0.f, 0.f, c, z);          // RZ
        a = th[i*3 + 1];
        __sincosf(0.5f*a, &z, &c);
        gate1q(s, i, c, 0.f, 0.f, -z, 0.f, -z, c, 0.f);         // RX
        a = th[i*3 + 2];
        __sincosf(0.5f*a, &z, &c);
        gate1q(s, i, c, -z, 0.f, 0.f, 0.f, 0.f, c, z);          // RZ
    }
    cnot(s, 0, 1); cnot(s, 1, 2); cnot(s, 2, 0);
}

__device__ void feature(cf* s, float t)
{
    #pragma unroll
    for (int i = 0; i < 3; i++) {
        float c, z;
        __sincosf(0.5f * PI_F * t * (float)(i + 1), &z, &c);
        gate1q(s, i, c, 0.f, -z, 0.f, z, 0.f, c, 0.f);          // RY
    }
}

__device__ float eval_circuit(const float* theta, float t)
{
    cf s[8];
    #pragma unroll
    for (int k = 0; k < 8; k++) { s[k].re = 0.f; s[k].im = 0.f; }
    s[0].re = 1.f;
    ansatz(s, theta);
    feature(s, t);
    ansatz(s, theta + 9);
    feature(s, t);
    ansatz(s, theta + 18);
    float e = 0.f;
    #pragma unroll
    for (int k = 0; k < 8; k++) {
        float p = s[k].re*s[k].re + s[k].im*s[k].im;
        e += (k < 4) ? p : -p;   // Z on qubit 0 (bit value 4)
    }
    return e;
}

// Trig-poly value f and scaled derivative D = f'(t)*h at t.
__device__ __forceinline__ void poly_fd(float tt, const float* ca,
                                        const float* cb, float& f, float& D)
{
    float c1v, s1v; __sincosf(PI_F * tt, &s1v, &c1v);
    f = fmaf(ca[1], c1v, ca[0]);
    f = fmaf(cb[1], s1v, f);
    float g = cb[1]*c1v - ca[1]*s1v;
    const float twoc = c1v + c1v;
    float ckm = 1.f, ck = c1v, skm = 0.f, sk = s1v;
    #pragma unroll
    for (int k = 2; k <= NHARM; k++) {
        float cn = fmaf(twoc, ck, -ckm);
        float sn = fmaf(twoc, sk, -skm);
        f = fmaf(ca[k], cn, f);
        f = fmaf(cb[k], sn, f);
        g = fmaf((float)k, cb[k]*cn - ca[k]*sn, g);
        ckm = ck; ck = cn; skm = sk; sk = sn;
    }
    D = g * (PI_F / (float)TBL);
}

// One block: samples -> DFT -> endpoint (f, f'h) -> cubic coeffs -> global.
__global__ void __launch_bounds__(THREADS)
precompute_kernel(const float* __restrict__ theta)
{
    __shared__ float fs[NSAMP];
    __shared__ float ca[NHARM + 1], cb[NHARM + 1];
    __shared__ float fv[TBL + 1], Dv[TBL + 1];
    const int tid = threadIdx.x;

    if (tid < NSAMP)
        fs[tid] = eval_circuit(theta, 2.0f * (float)tid / 25.0f);
    __syncthreads();

    if (tid < NSAMP) {
        float sum = 0.f;
        if (tid == 0) {
            for (int m = 0; m < NSAMP; m++) sum += fs[m];
            ca[0] = sum * (1.0f / 25.0f);
            cb[0] = 0.f;
        } else if (tid <= NHARM) {
            for (int m = 0; m < NSAMP; m++) {
                int r = (tid * m) % 25;
                float c, s; __sincosf(TWO_PI_F * (float)r * (1.0f/25.0f), &s, &c);
                sum += fs[m] * c;
            }
            ca[tid] = sum * (2.0f / 25.0f);
        } else {
            int k = tid - NHARM;
            for (int m = 0; m < NSAMP; m++) {
                int r = (k * m) % 25;
                float c, s; __sincosf(TWO_PI_F * (float)r * (1.0f/25.0f), &s, &c);
                sum += fs[m] * s;
            }
            cb[k] = sum * (2.0f / 25.0f);
        }
    }
    __syncthreads();

    // 257 endpoints; thread e does endpoint e, thread 0 also does endpoint 256.
    {
        float f, D;
        poly_fd((float)tid * (1.0f / (float)TBL), ca, cb, f, D);
        fv[tid] = f; Dv[tid] = D;
        if (tid == 0) {
            poly_fd(1.0f, ca, cb, f, D);
            fv[TBL] = f; Dv[TBL] = D;
        }
    }
    __syncthreads();

    // Hermite power-basis coeffs on u in [0,1): one interval per thread.
    {
        float f0 = fv[tid], f1 = fv[tid + 1];
        float D0 = Dv[tid], D1 = Dv[tid + 1];
        g_table[tid] = make_float4(
            f0,
            D0,
            3.f*(f1 - f0) - 2.f*D0 - D1,
            2.f*(f0 - f1) + D0 + D1);
    }
}

__device__ __forceinline__ float interp(float tt, const float4* tbl)
{
    float x = tt * (float)TBL;
    int i = min((int)x, TBL - 1);
    float u = x - (float)i;
    float4 c = tbl[i];
    return fmaf(fmaf(fmaf(c.w, u, c.z), u, c.y), u, c.x);
}

__global__ void __launch_bounds__(THREADS)
eval_kernel(const float* __restrict__ t, float* __restrict__ out, int n)
{
    __shared__ float4 tbl[TBL];
    tbl[threadIdx.x] = g_table[threadIdx.x];   // THREADS == TBL
    __syncthreads();

    const int v = blockIdx.x * THREADS + threadIdx.x;
    const int nvec = n >> 2;
    if (v < nvec) {
        float4 tv = __ldg(reinterpret_cast<const float4*>(t) + v);
        float4 ov;
        ov.x = interp(tv.x, tbl);
        ov.y = interp(tv.y, tbl);
        ov.z = interp(tv.z, tbl);
        ov.w = interp(tv.w, tbl);
        reinterpret_cast<float4*>(out)[v] = ov;
    }
    // tail (n not a multiple of 4)
    const int tail0 = nvec << 2;
    int i = tail0 + v;
    if (i < n)
        out[i] = interp(t[i], tbl);
}

extern "C" void kernel_launch(void* const* d_in, const int* in_sizes, int n_in,
                              void* d_out, int out_size)
{
    const float* t;
    const float* theta;
    if (n_in >= 2 && in_sizes[0] == 27 && in_sizes[1] != 27) {
        theta = (const float*)d_in[0];
        t     = (const float*)d_in[1];
    } else {
        t     = (const float*)d_in[0];
        theta = (const float*)d_in[1];
    }
    float* out = (float*)d_out;
    const int n = out_size;

    precompute_kernel<<<1, THREADS>>>(theta);

    const int nvec = (n + 3) >> 2;
    const int blocks = (nvec + THREADS - 1) / THREADS;   // 2048 at n = 2^21
    eval_kernel<<<blocks, THREADS>>>(t, out, n);
}

// round 8
// speedup vs baseline: 1.7494x; 1.0949x over previous
#include <cuda_runtime.h>
#include <math.h>

// ----------------------------------------------------------------------------
// QuantumBranch, two-kernel split + PDL overlap (round 8).
// expz0(t) = degree-12 trig polynomial in (pi*t), exactly.
//   K1 precompute (1 block): 25 circuit samples -> exact real DFT -> 256-entry
//      Hermite cubic table (float4 power basis) -> __device__ global.
//   K2 eval (1024 blocks, one wave): launched with PROGRAMMATIC stream
//      serialization -> starts WHILE K1 runs, stages its 2048 inputs into
//      smem (LDG.128 x2/thread), THEN cudaGridDependencySynchronize(), copies
//      the 4 KB table to smem, and interpolates 8 elements/thread.
// K1's duration and K2's input DRAM latency overlap instead of serializing.
// Cubic error (12pi)^4 h^4/384 ~ 1.2e-6 at TBL=256  << 1e-3 tolerance.
// ----------------------------------------------------------------------------

#define NSAMP 25
#define NHARM 12
#define TBL   256
#define THREADS 256
#define ELEMS_PER_BLOCK (THREADS * 8)
#define PI_F  3.14159265358979323846f
#define TWO_PI_F 6.28318530717958647692f

__device__ float4 g_table[TBL];

struct cf { float re, im; };

__device__ __forceinline__ void gate1q(cf* s, int wire,
    float u00r, float u00i, float u01r, float u01i,
    float u10r, float u10i, float u11r, float u11i)
{
    const int str = 4 >> wire;
    #pragma unroll
    for (int k = 0; k < 8; k++) {
        if (k & str) continue;
        cf a = s[k], b = s[k + str];
        s[k].re       = u00r*a.re - u00i*a.im + u01r*b.re - u01i*b.im;
        s[k].im       = u00r*a.im + u00i*a.re + u01r*b.im + u01i*b.re;
        s[k + str].re = u10r*a.re - u10i*a.im + u11r*b.re - u11i*b.im;
        s[k + str].im = u10r*a.im + u10i*a.re + u11r*b.im + u11i*b.re;
    }
}

__device__ __forceinline__ void cnot(cf* s, int ctrl, int tgt)
{
    const int sc = 4 >> ctrl, st = 4 >> tgt;
    #pragma unroll
    for (int k = 0; k < 8; k++) {
        if (!(k & sc) || (k & st)) continue;
        cf tmp = s[k]; s[k] = s[k + st]; s[k + st] = tmp;
    }
}

__device__ void ansatz(cf* s, const float* th)
{
    #pragma unroll
    for (int i = 0; i < 3; i++) {
        float a = th[i*3 + 0];
        float c, z; __sincosf(0.5f*a, &z, &c);
        gate1q(s, i, c, -z, 0.f, 0.f, 0.f, 0.f, c, z);          // RZ
        a = th[i*3 + 1];
        __sincosf(0.5f*a, &z, &c);
        gate1q(s, i, c, 0.f, 0.f, -z, 0.f, -z, c, 0.f);         // RX
        a = th[i*3 + 2];
        __sincosf(0.5f*a, &z, &c);
        gate1q(s, i, c, -z, 0.f, 0.f, 0.f, 0.f, c, z);          // RZ
    }
    cnot(s, 0, 1); cnot(s, 1, 2); cnot(s, 2, 0);
}

__device__ void feature(cf* s, float t)
{
    #pragma unroll
    for (int i = 0; i < 3; i++) {
        float c, z;
        __sincosf(0.5f * PI_F * t * (float)(i + 1), &z, &c);
        gate1q(s, i, c, 0.f, -z, 0.f, z, 0.f, c, 0.f);          // RY
    }
}

__device__ float eval_circuit(const float* theta, float t)
{
    cf s[8];
    #pragma unroll
    for (int k = 0; k < 8; k++) { s[k].re = 0.f; s[k].im = 0.f; }
    s[0].re = 1.f;
    ansatz(s, theta);
    feature(s, t);
    ansatz(s, theta + 9);
    feature(s, t);
    ansatz(s, theta + 18);
    float e = 0.f;
    #pragma unroll
    for (int k = 0; k < 8; k++) {
        float p = s[k].re*s[k].re + s[k].im*s[k].im;
        e += (k < 4) ? p : -p;   // Z on qubit 0 (bit value 4)
    }
    return e;
}

// Trig-poly value f and scaled derivative D = f'(t)*h at t.
__device__ __forceinline__ void poly_fd(float tt, const float* ca,
                                        const float* cb, float& f, float& D)
{
    float c1v, s1v; __sincosf(PI_F * tt, &s1v, &c1v);
    f = fmaf(ca[1], c1v, ca[0]);
    f = fmaf(cb[1], s1v, f);
    float g = cb[1]*c1v - ca[1]*s1v;
    const float twoc = c1v + c1v;
    float ckm = 1.f, ck = c1v, skm = 0.f, sk = s1v;
    #pragma unroll
    for (int k = 2; k <= NHARM; k++) {
        float cn = fmaf(twoc, ck, -ckm);
        float sn = fmaf(twoc, sk, -skm);
        f = fmaf(ca[k], cn, f);
        f = fmaf(cb[k], sn, f);
        g = fmaf((float)k, cb[k]*cn - ca[k]*sn, g);
        ckm = ck; ck = cn; skm = sk; sk = sn;
    }
    D = g * (PI_F / (float)TBL);
}

// One block: samples -> DFT -> endpoint (f, f'h) -> cubic coeffs -> global.
__global__ void __launch_bounds__(THREADS)
precompute_kernel(const float* __restrict__ theta)
{
    __shared__ float fs[NSAMP];
    __shared__ float ca[NHARM + 1], cb[NHARM + 1];
    __shared__ float fv[TBL + 1], Dv[TBL + 1];
    const int tid = threadIdx.x;

    if (tid < NSAMP)
        fs[tid] = eval_circuit(theta, 2.0f * (float)tid / 25.0f);
    __syncthreads();

    if (tid < NSAMP) {
        float sum = 0.f;
        if (tid == 0) {
            for (int m = 0; m < NSAMP; m++) sum += fs[m];
            ca[0] = sum * (1.0f / 25.0f);
            cb[0] = 0.f;
        } else if (tid <= NHARM) {
            for (int m = 0; m < NSAMP; m++) {
                int r = (tid * m) % 25;
                float c, s; __sincosf(TWO_PI_F * (float)r * (1.0f/25.0f), &s, &c);
                sum += fs[m] * c;
            }
            ca[tid] = sum * (2.0f / 25.0f);
        } else {
            int k = tid - NHARM;
            for (int m = 0; m < NSAMP; m++) {
                int r = (k * m) % 25;
                float c, s; __sincosf(TWO_PI_F * (float)r * (1.0f/25.0f), &s, &c);
                sum += fs[m] * s;
            }
            cb[k] = sum * (2.0f / 25.0f);
        }
    }
    __syncthreads();

    {
        float f, D;
        poly_fd((float)tid * (1.0f / (float)TBL), ca, cb, f, D);
        fv[tid] = f; Dv[tid] = D;
        if (tid == 0) {
            poly_fd(1.0f, ca, cb, f, D);
            fv[TBL] = f; Dv[TBL] = D;
        }
    }
    __syncthreads();

    {
        float f0 = fv[tid], f1 = fv[tid + 1];
        float D0 = Dv[tid], D1 = Dv[tid + 1];
        g_table[tid] = make_float4(
            f0,
            D0,
            3.f*(f1 - f0) - 2.f*D0 - D1,
            2.f*(f0 - f1) + D0 + D1);
    }
}

__device__ __forceinline__ float interp(float tt, const float4* tbl)
{
    float x = tt * (float)TBL;
    int i = min(max((int)x, 0), TBL - 1);
    float u = x - (float)i;
    float4 c = tbl[i];
    return fmaf(fmaf(fmaf(c.w, u, c.z), u, c.y), u, c.x);
}

__global__ void __launch_bounds__(THREADS, 8)
eval_kernel(const float* __restrict__ t, float* __restrict__ out, int n)
{
    __shared__ float4 tin[2 * THREADS];   // 8 KB input staging
    __shared__ float4 tbl[TBL];           // 4 KB table

    const int tid = threadIdx.x;
    const int vbase = blockIdx.x * (ELEMS_PER_BLOCK / 4);  // float4 index
    const bool full = (vbase + 2 * THREADS) * 4 <= n;

    // ---- stage inputs FIRST: overlaps the still-running precompute kernel ---
    if (full) {
        const float4* in4 = reinterpret_cast<const float4*>(t);
        tin[tid]           = __ldg(in4 + vbase + tid);
        tin[tid + THREADS] = __ldg(in4 + vbase + THREADS + tid);
    }

    // ---- wait for precompute completion (PDL), then grab the table ----------
    cudaGridDependencySynchronize();
    tbl[tid] = g_table[tid];              // THREADS == TBL
    __syncthreads();

    if (full) {
        float4* out4 = reinterpret_cast<float4*>(out);
        #pragma unroll
        for (int j = 0; j < 2; j++) {
            float4 tv = tin[tid + j * THREADS];
            float4 ov;
            ov.x = interp(tv.x, tbl);
            ov.y = interp(tv.y, tbl);
            ov.z = interp(tv.z, tbl);
            ov.w = interp(tv.w, tbl);
            out4[vbase + j * THREADS + tid] = ov;
        }
    } else {
        for (int i = vbase * 4 + tid; i < n; i += THREADS)
            out[i] = interp(t[i], tbl);
    }
}

extern "C" void kernel_launch(void* const* d_in, const int* in_sizes, int n_in,
                              void* d_out, int out_size)
{
    const float* t;
    const float* theta;
    if (n_in >= 2 && in_sizes[0] == 27 && in_sizes[1] != 27) {
        theta = (const float*)d_in[0];
        t     = (const float*)d_in[1];
    } else {
        t     = (const float*)d_in[0];
        theta = (const float*)d_in[1];
    }
    float* out = (float*)d_out;
    const int n = out_size;

    precompute_kernel<<<1, THREADS>>>(theta);

    // eval with programmatic dependent launch: blocks start while precompute
    // runs; cudaGridDependencySynchronize() inside gates the g_table read.
    const int blocks = (n + ELEMS_PER_BLOCK - 1) / ELEMS_PER_BLOCK;  // 1024

    cudaLaunchConfig_t cfg = {};
    cfg.gridDim  = dim3(blocks, 1, 1);
    cfg.blockDim = dim3(THREADS, 1, 1);
    cfg.dynamicSmemBytes = 0;
    cfg.stream = 0;   // legacy default stream (same as <<<>>>)
    cudaLaunchAttribute attrs[1];
    attrs[0].id = cudaLaunchAttributeProgrammaticStreamSerialization;
    attrs[0].val.programmaticStreamSerializationAllowed = 1;
    cfg.attrs = attrs;
    cfg.numAttrs = 1;

    cudaLaunchKernelEx(&cfg, eval_kernel, t, out, n);
}